// round 6
// baseline (speedup 1.0000x reference)
#include <cuda_runtime.h>
#include <cuda_fp16.h>

#define N_NODES 50000
#define N_EDGES 1600000
#define FDIM    128
#define GN      8
#define CAP     128          // per-node edge bucket capacity (max degree ~58)

// Scratch (static __device__ arrays: allocation-free per harness rules)
static __device__ __half2 g_hh[(size_t)N_NODES * (FDIM / 2)];   // 12.8 MB
static __device__ float g_sd[N_NODES];
static __device__ float g_ss[N_NODES];
static __device__ float g_Wp[FDIM * FDIM];
static __device__ int   g_cnt[N_NODES];
static __device__ unsigned int g_csr[(size_t)N_NODES * CAP];    // 25.6 MB: src(16b) | fp16 score(16b)

#define FMA_F32X2(d, a, b, c) \
    asm("fma.rn.f32x2 %0, %1, %2, %3;" : "=l"(d) : "l"(a), "l"(b), "l"(c))

// ---------------------------------------------------------------------------
// Setup: pack W into k-pair-interleaved layout AND zero the bucket counters.
// ---------------------------------------------------------------------------
__global__ void setup_kernel(const float* __restrict__ W) {
    int i = blockIdx.x * blockDim.x + threadIdx.x;
    if (i < FDIM * FDIM) {
        int kp = i >> 8;
        int j  = i & 255;
        g_Wp[i] = W[(2 * kp + (j & 1)) * FDIM + (j >> 1)];
    }
    if (i < N_NODES) g_cnt[i] = 0;
}

// ---------------------------------------------------------------------------
// h = X @ W via packed f32x2 FFMA + per-node attention scores. h in fp16.
// ---------------------------------------------------------------------------
__global__ __launch_bounds__(256) void gemm_score_kernel(
    const float* __restrict__ X, const float* __restrict__ attn)
{
    const int warp = threadIdx.x >> 5;
    const int lane = threadIdx.x & 31;
    const int node0 = (blockIdx.x * 8 + warp) * GN;

    __shared__ __align__(16) float xs[8][GN][FDIM];   // 32 KB

    #pragma unroll
    for (int n = 0; n < GN; n++) {
        int node = node0 + n;
        float4 v = make_float4(0.f, 0.f, 0.f, 0.f);
        if (node < N_NODES)
            v = reinterpret_cast<const float4*>(X + (size_t)node * FDIM)[lane];
        reinterpret_cast<float4*>(xs[warp][n])[lane] = v;
    }
    __syncwarp();

    unsigned long long acc[GN][4];
    #pragma unroll
    for (int n = 0; n < GN; n++)
        acc[n][0] = acc[n][1] = acc[n][2] = acc[n][3] = 0ull;

    const ulonglong2* wp = reinterpret_cast<const ulonglong2*>(g_Wp) + lane * 2;

    #pragma unroll 2
    for (int kp = 0; kp < FDIM / 2; kp++) {
        ulonglong2 wa = wp[kp * 64 + 0];
        ulonglong2 wb = wp[kp * 64 + 1];
        #pragma unroll
        for (int n = 0; n < GN; n++) {
            unsigned long long xx =
                *reinterpret_cast<const unsigned long long*>(&xs[warp][n][kp * 2]);
            FMA_F32X2(acc[n][0], xx, wa.x, acc[n][0]);
            FMA_F32X2(acc[n][1], xx, wa.y, acc[n][1]);
            FMA_F32X2(acc[n][2], xx, wb.x, acc[n][2]);
            FMA_F32X2(acc[n][3], xx, wb.y, acc[n][3]);
        }
    }

    float4 ad = reinterpret_cast<const float4*>(attn)[lane];
    float4 as = reinterpret_cast<const float4*>(attn + FDIM)[lane];

    #pragma unroll
    for (int n = 0; n < GN; n++) {
        float r[4];
        #pragma unroll
        for (int c = 0; c < 4; c++) {
            float2 u = *reinterpret_cast<float2*>(&acc[n][c]);
            r[c] = u.x + u.y;
        }
        int node = node0 + n;
        float pd = r[0] * ad.x + r[1] * ad.y + r[2] * ad.z + r[3] * ad.w;
        float ps = r[0] * as.x + r[1] * as.y + r[2] * as.z + r[3] * as.w;
        #pragma unroll
        for (int off = 16; off; off >>= 1) {
            pd += __shfl_xor_sync(0xffffffffu, pd, off);
            ps += __shfl_xor_sync(0xffffffffu, ps, off);
        }
        if (node < N_NODES) {
            __half2 p0 = __floats2half2_rn(r[0], r[1]);
            __half2 p1 = __floats2half2_rn(r[2], r[3]);
            uint2 packed;
            packed.x = *reinterpret_cast<unsigned int*>(&p0);
            packed.y = *reinterpret_cast<unsigned int*>(&p1);
            reinterpret_cast<uint2*>(g_hh)[(size_t)node * 32 + lane] = packed;
            if (lane == 0) { g_sd[node] = pd; g_ss[node] = ps; }
        }
    }
}

// ---------------------------------------------------------------------------
// Direct bucket scatter: pos = atomicAdd(cnt[dst]); ONE packed uint32
// (src | fp16 score << 16) random store per edge. 2 edges per thread.
// ---------------------------------------------------------------------------
__global__ __launch_bounds__(256) void scatter_kernel(const int4* __restrict__ E4) {
    int i = blockIdx.x * blockDim.x + threadIdx.x;
    if (i >= N_EDGES / 2) return;
    int4 e = E4[i];             // (dst0, src0, dst1, src1)

    float sc0 = g_sd[e.x] + g_ss[e.y];
    sc0 = sc0 > 0.f ? sc0 : 0.2f * sc0;
    sc0 = fminf(2.f, fmaxf(-2.f, sc0));
    float s0 = __expf(sc0);

    float sc1 = g_sd[e.z] + g_ss[e.w];
    sc1 = sc1 > 0.f ? sc1 : 0.2f * sc1;
    sc1 = fminf(2.f, fmaxf(-2.f, sc1));
    float s1 = __expf(sc1);

    unsigned int m0 = (unsigned int)e.y |
        ((unsigned int)__half_as_ushort(__float2half_rn(s0)) << 16);
    unsigned int m1 = (unsigned int)e.w |
        ((unsigned int)__half_as_ushort(__float2half_rn(s1)) << 16);

    int p0 = atomicAdd(&g_cnt[e.x], 1);
    g_csr[(unsigned int)e.x * CAP + p0] = m0;
    int p1 = atomicAdd(&g_cnt[e.z], 1);
    g_csr[(unsigned int)e.z * CAP + p1] = m1;
}

// ---------------------------------------------------------------------------
// One warp per dst node, SPLIT-WARP: lanes 0-15 take even edges, 16-31 odd.
// Each lane loads 16B (8 fp16 h-values) per edge via LDG.128. fp32 accum,
// halves combined with shfl_xor(16), softmax-normalize, STG.128 store.
// ---------------------------------------------------------------------------
__global__ __launch_bounds__(256) void agg_kernel(float* __restrict__ out) {
    int w    = (blockIdx.x * blockDim.x + threadIdx.x) >> 5;
    int lane = threadIdx.x & 31;
    if (w >= N_NODES) return;

    const int cnt  = g_cnt[w];
    const int half = lane >> 4;          // 0 or 1
    const int hl   = lane & 15;
    const unsigned int* row = g_csr + (unsigned int)w * CAP;
    const uint4* hh = reinterpret_cast<const uint4*>(g_hh);   // 16 uint4 per node row

    float a0=0.f,a1=0.f,a2=0.f,a3=0.f,a4=0.f,a5=0.f,a6=0.f,a7=0.f;
    float ssum = 0.f;

    for (int e = 0; e < cnt; e += 8) {
        #pragma unroll
        for (int u = 0; u < 4; u++) {
            int idx = e + u * 2 + half;
            unsigned int m = 0u;                 // src=0, weight bits=0 -> +0.0
            if (idx < cnt) m = row[idx];
            unsigned int src = m & 0xFFFFu;
            float wt = __half2float(__ushort_as_half((unsigned short)(m >> 16)));
            uint4 v = hh[src * 16 + hl];
            float2 f0 = __half22float2(*reinterpret_cast<const __half2*>(&v.x));
            float2 f1 = __half22float2(*reinterpret_cast<const __half2*>(&v.y));
            float2 f2 = __half22float2(*reinterpret_cast<const __half2*>(&v.z));
            float2 f3 = __half22float2(*reinterpret_cast<const __half2*>(&v.w));
            a0 += wt * f0.x;  a1 += wt * f0.y;
            a2 += wt * f1.x;  a3 += wt * f1.y;
            a4 += wt * f2.x;  a5 += wt * f2.y;
            a6 += wt * f3.x;  a7 += wt * f3.y;
            ssum += wt;
        }
    }

    // combine the two half-warps (lane i <-> lane i^16 hold same columns)
    a0 += __shfl_xor_sync(0xffffffffu, a0, 16);
    a1 += __shfl_xor_sync(0xffffffffu, a1, 16);
    a2 += __shfl_xor_sync(0xffffffffu, a2, 16);
    a3 += __shfl_xor_sync(0xffffffffu, a3, 16);
    a4 += __shfl_xor_sync(0xffffffffu, a4, 16);
    a5 += __shfl_xor_sync(0xffffffffu, a5, 16);
    a6 += __shfl_xor_sync(0xffffffffu, a6, 16);
    a7 += __shfl_xor_sync(0xffffffffu, a7, 16);
    ssum += __shfl_xor_sync(0xffffffffu, ssum, 16);

    float inv = (ssum > 0.f) ? (1.f / ssum) : 0.f;
    // lane stores cols [hl*8 + half*4, +4): half 0 -> a0..a3, half 1 -> a4..a7
    float4 r = half ? make_float4(a4, a5, a6, a7) : make_float4(a0, a1, a2, a3);
    r.x *= inv; r.y *= inv; r.z *= inv; r.w *= inv;
    *reinterpret_cast<float4*>(out + (unsigned int)w * FDIM + hl * 8 + half * 4) = r;
}

// ---------------------------------------------------------------------------
extern "C" void kernel_launch(void* const* d_in, const int* in_sizes, int n_in,
                              void* d_out, int out_size)
{
    const float* X    = (const float*)d_in[0];   // node_states (50000,128)
    const int4*  E4   = (const int4*) d_in[1];   // edges as 2-edge packs
    const float* W    = (const float*)d_in[2];   // kernel (128,128)
    const float* attn = (const float*)d_in[3];   // kernel_attention (256,1)
    float* out = (float*)d_out;

    setup_kernel<<<(N_NODES + 255) / 256, 256>>>(W);
    gemm_score_kernel<<<(N_NODES + 63) / 64, 256>>>(X, attn);
    scatter_kernel<<<(N_EDGES / 2 + 255) / 256, 256>>>(E4);
    agg_kernel<<<(N_NODES * 32 + 255) / 256, 256>>>(out);
}

// round 7
// speedup vs baseline: 1.4884x; 1.4884x over previous
#include <cuda_runtime.h>
#include <cuda_fp16.h>

#define N_NODES 50000
#define N_EDGES 1600000
#define FDIM    128
#define GN      8
#define CAP     128          // per-node edge bucket capacity (max degree ~58)

// Scratch (static __device__ arrays: allocation-free per harness rules)
static __device__ __half2 g_hh[(size_t)N_NODES * (FDIM / 2)];   // 12.8 MB
static __device__ float g_sd[N_NODES];
static __device__ float g_ss[N_NODES];
static __device__ float g_Wp[FDIM * FDIM];
static __device__ int   g_cnt[N_NODES];
static __device__ int2  g_csr[(size_t)N_NODES * CAP];           // 51.2 MB (src, score-bits)

#define FMA_F32X2(d, a, b, c) \
    asm("fma.rn.f32x2 %0, %1, %2, %3;" : "=l"(d) : "l"(a), "l"(b), "l"(c))

__device__ __forceinline__ unsigned long long pack_f2(float2 v) {
    return *reinterpret_cast<unsigned long long*>(&v);
}

// ---------------------------------------------------------------------------
// Setup: pack W into k-pair-interleaved layout AND zero the bucket counters.
// ---------------------------------------------------------------------------
__global__ void setup_kernel(const float* __restrict__ W) {
    int i = blockIdx.x * blockDim.x + threadIdx.x;
    if (i < FDIM * FDIM) {
        int kp = i >> 8;
        int j  = i & 255;
        g_Wp[i] = W[(2 * kp + (j & 1)) * FDIM + (j >> 1)];
    }
    if (i < N_NODES) g_cnt[i] = 0;
}

// ---------------------------------------------------------------------------
// h = X @ W via packed f32x2 FFMA + per-node attention scores. h in fp16.
// ---------------------------------------------------------------------------
__global__ __launch_bounds__(256) void gemm_score_kernel(
    const float* __restrict__ X, const float* __restrict__ attn)
{
    const int warp = threadIdx.x >> 5;
    const int lane = threadIdx.x & 31;
    const int node0 = (blockIdx.x * 8 + warp) * GN;

    __shared__ __align__(16) float xs[8][GN][FDIM];   // 32 KB

    #pragma unroll
    for (int n = 0; n < GN; n++) {
        int node = node0 + n;
        float4 v = make_float4(0.f, 0.f, 0.f, 0.f);
        if (node < N_NODES)
            v = reinterpret_cast<const float4*>(X + (size_t)node * FDIM)[lane];
        reinterpret_cast<float4*>(xs[warp][n])[lane] = v;
    }
    __syncwarp();

    unsigned long long acc[GN][4];
    #pragma unroll
    for (int n = 0; n < GN; n++)
        acc[n][0] = acc[n][1] = acc[n][2] = acc[n][3] = 0ull;

    const ulonglong2* wp = reinterpret_cast<const ulonglong2*>(g_Wp) + lane * 2;

    #pragma unroll 2
    for (int kp = 0; kp < FDIM / 2; kp++) {
        ulonglong2 wa = wp[kp * 64 + 0];
        ulonglong2 wb = wp[kp * 64 + 1];
        #pragma unroll
        for (int n = 0; n < GN; n++) {
            unsigned long long xx =
                *reinterpret_cast<const unsigned long long*>(&xs[warp][n][kp * 2]);
            FMA_F32X2(acc[n][0], xx, wa.x, acc[n][0]);
            FMA_F32X2(acc[n][1], xx, wa.y, acc[n][1]);
            FMA_F32X2(acc[n][2], xx, wb.x, acc[n][2]);
            FMA_F32X2(acc[n][3], xx, wb.y, acc[n][3]);
        }
    }

    float4 ad = reinterpret_cast<const float4*>(attn)[lane];
    float4 as = reinterpret_cast<const float4*>(attn + FDIM)[lane];

    #pragma unroll
    for (int n = 0; n < GN; n++) {
        float r[4];
        #pragma unroll
        for (int c = 0; c < 4; c++) {
            float2 u = *reinterpret_cast<float2*>(&acc[n][c]);
            r[c] = u.x + u.y;
        }
        int node = node0 + n;
        float pd = r[0] * ad.x + r[1] * ad.y + r[2] * ad.z + r[3] * ad.w;
        float ps = r[0] * as.x + r[1] * as.y + r[2] * as.z + r[3] * as.w;
        #pragma unroll
        for (int off = 16; off; off >>= 1) {
            pd += __shfl_xor_sync(0xffffffffu, pd, off);
            ps += __shfl_xor_sync(0xffffffffu, ps, off);
        }
        if (node < N_NODES) {
            __half2 p0 = __floats2half2_rn(r[0], r[1]);
            __half2 p1 = __floats2half2_rn(r[2], r[3]);
            uint2 packed;
            packed.x = *reinterpret_cast<unsigned int*>(&p0);
            packed.y = *reinterpret_cast<unsigned int*>(&p1);
            reinterpret_cast<uint2*>(g_hh)[(size_t)node * 32 + lane] = packed;
            if (lane == 0) { g_sd[node] = pd; g_ss[node] = ps; }
        }
    }
}

// ---------------------------------------------------------------------------
// Direct bucket scatter: pos = atomicAdd(cnt[dst]); one int2 (src, score)
// store per edge. 2 edges per thread via int4.  (round-5 measured-good form)
// ---------------------------------------------------------------------------
__global__ __launch_bounds__(256) void scatter_kernel(const int4* __restrict__ E4) {
    int i = blockIdx.x * blockDim.x + threadIdx.x;
    if (i >= N_EDGES / 2) return;
    int4 e = E4[i];             // (dst0, src0, dst1, src1)

    float sc0 = g_sd[e.x] + g_ss[e.y];
    sc0 = sc0 > 0.f ? sc0 : 0.2f * sc0;
    sc0 = fminf(2.f, fmaxf(-2.f, sc0));
    float s0 = __expf(sc0);

    float sc1 = g_sd[e.z] + g_ss[e.w];
    sc1 = sc1 > 0.f ? sc1 : 0.2f * sc1;
    sc1 = fminf(2.f, fmaxf(-2.f, sc1));
    float s1 = __expf(sc1);

    int p0 = atomicAdd(&g_cnt[e.x], 1);
    g_csr[(size_t)e.x * CAP + p0] = make_int2(e.y, __float_as_int(s0));
    int p1 = atomicAdd(&g_cnt[e.z], 1);
    g_csr[(size_t)e.z * CAP + p1] = make_int2(e.w, __float_as_int(s1));
}

// ---------------------------------------------------------------------------
// One warp per dst node (round-5 memory pattern): lane loads uint2 (4 fp16)
// of h[src]; accumulation now via packed fma.rn.f32x2 (2 FFMA2 instead of
// 4 FFMA per edge per lane) to cut issue pressure in the bound pipe.
// ---------------------------------------------------------------------------
__global__ __launch_bounds__(256) void agg_kernel(float* __restrict__ out) {
    int w    = (blockIdx.x * blockDim.x + threadIdx.x) >> 5;
    int lane = threadIdx.x & 31;
    if (w >= N_NODES) return;

    int cnt = g_cnt[w];
    const int2* row = g_csr + (size_t)w * CAP;
    const uint2* hh = reinterpret_cast<const uint2*>(g_hh);

    unsigned long long accA = 0ull, accB = 0ull;   // packed (c0,c1), (c2,c3)
    float ssum = 0.f;

    #define ACCUM(V, WT) { \
        float2 f0 = __half22float2(*reinterpret_cast<__half2*>(&(V).x)); \
        float2 f1 = __half22float2(*reinterpret_cast<__half2*>(&(V).y)); \
        unsigned long long ww = pack_f2(make_float2((WT), (WT))); \
        FMA_F32X2(accA, ww, pack_f2(f0), accA); \
        FMA_F32X2(accB, ww, pack_f2(f1), accB); }

    int e = 0;
    for (; e + 4 <= cnt; e += 4) {
        int2 e0 = row[e],     e1 = row[e + 1];
        int2 e2 = row[e + 2], e3 = row[e + 3];
        float w0 = __int_as_float(e0.y), w1 = __int_as_float(e1.y);
        float w2 = __int_as_float(e2.y), w3 = __int_as_float(e3.y);
        uint2 v0 = hh[(size_t)e0.x * 32 + lane];
        uint2 v1 = hh[(size_t)e1.x * 32 + lane];
        uint2 v2 = hh[(size_t)e2.x * 32 + lane];
        uint2 v3 = hh[(size_t)e3.x * 32 + lane];
        ACCUM(v0, w0) ACCUM(v1, w1) ACCUM(v2, w2) ACCUM(v3, w3)
        ssum += (w0 + w1) + (w2 + w3);
    }
    for (; e < cnt; e++) {
        int2 ee = row[e];
        float w0 = __int_as_float(ee.y);
        uint2 v0 = hh[(size_t)ee.x * 32 + lane];
        ACCUM(v0, w0)
        ssum += w0;
    }
    #undef ACCUM

    float2 rA = *reinterpret_cast<float2*>(&accA);
    float2 rB = *reinterpret_cast<float2*>(&accB);
    float inv = (ssum > 0.f) ? (1.f / ssum) : 0.f;
    reinterpret_cast<float4*>(out)[(size_t)w * 32 + lane] =
        make_float4(rA.x * inv, rA.y * inv, rB.x * inv, rB.y * inv);
}

// ---------------------------------------------------------------------------
extern "C" void kernel_launch(void* const* d_in, const int* in_sizes, int n_in,
                              void* d_out, int out_size)
{
    const float* X    = (const float*)d_in[0];   // node_states (50000,128)
    const int4*  E4   = (const int4*) d_in[1];   // edges as 2-edge packs
    const float* W    = (const float*)d_in[2];   // kernel (128,128)
    const float* attn = (const float*)d_in[3];   // kernel_attention (256,1)
    float* out = (float*)d_out;

    setup_kernel<<<(N_NODES + 255) / 256, 256>>>(W);
    gemm_score_kernel<<<(N_NODES + 63) / 64, 256>>>(X, attn);
    scatter_kernel<<<(N_EDGES / 2 + 255) / 256, 256>>>(E4);
    agg_kernel<<<(N_NODES * 32 + 255) / 256, 256>>>(out);
}

// round 8
// speedup vs baseline: 1.5104x; 1.0148x over previous
#include <cuda_runtime.h>
#include <cuda_fp16.h>

#define N_NODES 50000
#define N_EDGES 1600000
#define FDIM    128
#define GN      8
#define CAP     128          // per-node edge bucket capacity (max degree ~58)

#define GEMM_BLOCKS   ((N_NODES + 63) / 64)          // 782
#define SCAT_BLOCKS   ((N_EDGES / 2 + 255) / 256)    // 3125
#define PACK_BLOCKS   196                            // covers 50K pack/zero ids
#define WDWS_BLOCKS   32                             // 256 warp-outputs for wd/ws

// Scratch (static __device__ arrays: allocation-free per harness rules)
static __device__ __half2 g_hh[(size_t)N_NODES * (FDIM / 2)];   // 12.8 MB
static __device__ float g_sd[N_NODES];
static __device__ float g_ss[N_NODES];
static __device__ float g_Wp[FDIM * FDIM];
static __device__ float g_wd[FDIM];      // W @ a_dst
static __device__ float g_ws[FDIM];      // W @ a_src
static __device__ int   g_cnt[N_NODES];
static __device__ int2  g_csr[(size_t)N_NODES * CAP];           // (src, score-bits)

#define FMA_F32X2(d, a, b, c) \
    asm("fma.rn.f32x2 %0, %1, %2, %3;" : "=l"(d) : "l"(a), "l"(b), "l"(c))

__device__ __forceinline__ unsigned long long pack_f2(float2 v) {
    return *reinterpret_cast<unsigned long long*>(&v);
}

// ---------------------------------------------------------------------------
// Setup: pack W (k-pair-interleave), zero bucket counters, and compute
// wd = W @ a_dst, ws = W @ a_src (warp per output row-dot, blocks >= 196).
// ---------------------------------------------------------------------------
__global__ __launch_bounds__(256) void setup_kernel(
    const float* __restrict__ W, const float* __restrict__ attn)
{
    if (blockIdx.x < PACK_BLOCKS) {
        int i = blockIdx.x * 256 + threadIdx.x;
        if (i < FDIM * FDIM) {
            int kp = i >> 8;
            int j  = i & 255;
            g_Wp[i] = W[(2 * kp + (j & 1)) * FDIM + (j >> 1)];
        }
        if (i < N_NODES) g_cnt[i] = 0;
    } else {
        // 32 blocks x 8 warps = 256 outputs: o<128 -> wd[o], else ws[o-128]
        int warp = threadIdx.x >> 5;
        int lane = threadIdx.x & 31;
        int o = (blockIdx.x - PACK_BLOCKS) * 8 + warp;
        int k = o & 127;
        int which = o >> 7;
        float4 wv = reinterpret_cast<const float4*>(W + k * FDIM)[lane];
        float4 av = reinterpret_cast<const float4*>(attn + which * FDIM)[lane];
        float d = wv.x * av.x + wv.y * av.y + wv.z * av.z + wv.w * av.w;
        #pragma unroll
        for (int off = 16; off; off >>= 1)
            d += __shfl_xor_sync(0xffffffffu, d, off);
        if (lane == 0) {
            if (which == 0) g_wd[k] = d; else g_ws[k] = d;
        }
    }
}

// ---------------------------------------------------------------------------
// Per-node scores: sd[n] = X[n]·wd, ss[n] = X[n]·ws. One warp per node.
// ---------------------------------------------------------------------------
__global__ __launch_bounds__(256) void score_kernel(const float* __restrict__ X)
{
    int n    = (blockIdx.x * blockDim.x + threadIdx.x) >> 5;
    int lane = threadIdx.x & 31;
    if (n >= N_NODES) return;
    float4 xv = reinterpret_cast<const float4*>(X + (size_t)n * FDIM)[lane];
    float4 wd = reinterpret_cast<const float4*>(g_wd)[lane];
    float4 ws = reinterpret_cast<const float4*>(g_ws)[lane];
    float pd = xv.x * wd.x + xv.y * wd.y + xv.z * wd.z + xv.w * wd.w;
    float ps = xv.x * ws.x + xv.y * ws.y + xv.z * ws.z + xv.w * ws.w;
    #pragma unroll
    for (int off = 16; off; off >>= 1) {
        pd += __shfl_xor_sync(0xffffffffu, pd, off);
        ps += __shfl_xor_sync(0xffffffffu, ps, off);
    }
    if (lane == 0) { g_sd[n] = pd; g_ss[n] = ps; }
}

// ---------------------------------------------------------------------------
// FUSED: blocks [0, GEMM_BLOCKS) compute h = X@W (fp16 store, f32x2 FFMA);
// blocks [GEMM_BLOCKS, +SCAT_BLOCKS) scatter edges into buckets using the
// precomputed scores. Independent work overlaps within one launch.
// ---------------------------------------------------------------------------
__global__ __launch_bounds__(256) void fused_kernel(
    const float* __restrict__ X, const int4* __restrict__ E4)
{
    if (blockIdx.x < GEMM_BLOCKS) {
        // ---------------- GEMM branch ----------------
        const int warp = threadIdx.x >> 5;
        const int lane = threadIdx.x & 31;
        const int node0 = (blockIdx.x * 8 + warp) * GN;

        __shared__ __align__(16) float xs[8][GN][FDIM];   // 32 KB

        #pragma unroll
        for (int n = 0; n < GN; n++) {
            int node = node0 + n;
            float4 v = make_float4(0.f, 0.f, 0.f, 0.f);
            if (node < N_NODES)
                v = reinterpret_cast<const float4*>(X + (size_t)node * FDIM)[lane];
            reinterpret_cast<float4*>(xs[warp][n])[lane] = v;
        }
        __syncwarp();

        unsigned long long acc[GN][4];
        #pragma unroll
        for (int n = 0; n < GN; n++)
            acc[n][0] = acc[n][1] = acc[n][2] = acc[n][3] = 0ull;

        const ulonglong2* wp = reinterpret_cast<const ulonglong2*>(g_Wp) + lane * 2;

        #pragma unroll 2
        for (int kp = 0; kp < FDIM / 2; kp++) {
            ulonglong2 wa = wp[kp * 64 + 0];
            ulonglong2 wb = wp[kp * 64 + 1];
            #pragma unroll
            for (int n = 0; n < GN; n++) {
                unsigned long long xx =
                    *reinterpret_cast<const unsigned long long*>(&xs[warp][n][kp * 2]);
                FMA_F32X2(acc[n][0], xx, wa.x, acc[n][0]);
                FMA_F32X2(acc[n][1], xx, wa.y, acc[n][1]);
                FMA_F32X2(acc[n][2], xx, wb.x, acc[n][2]);
                FMA_F32X2(acc[n][3], xx, wb.y, acc[n][3]);
            }
        }

        #pragma unroll
        for (int n = 0; n < GN; n++) {
            int node = node0 + n;
            if (node < N_NODES) {
                float r[4];
                #pragma unroll
                for (int c = 0; c < 4; c++) {
                    float2 u = *reinterpret_cast<float2*>(&acc[n][c]);
                    r[c] = u.x + u.y;
                }
                __half2 p0 = __floats2half2_rn(r[0], r[1]);
                __half2 p1 = __floats2half2_rn(r[2], r[3]);
                uint2 packed;
                packed.x = *reinterpret_cast<unsigned int*>(&p0);
                packed.y = *reinterpret_cast<unsigned int*>(&p1);
                reinterpret_cast<uint2*>(g_hh)[(size_t)node * 32 + lane] = packed;
            }
        }
    } else {
        // ---------------- scatter branch ----------------
        int i = (blockIdx.x - GEMM_BLOCKS) * 256 + threadIdx.x;
        if (i >= N_EDGES / 2) return;
        int4 e = E4[i];             // (dst0, src0, dst1, src1)

        float sc0 = g_sd[e.x] + g_ss[e.y];
        sc0 = sc0 > 0.f ? sc0 : 0.2f * sc0;
        sc0 = fminf(2.f, fmaxf(-2.f, sc0));
        float s0 = __expf(sc0);

        float sc1 = g_sd[e.z] + g_ss[e.w];
        sc1 = sc1 > 0.f ? sc1 : 0.2f * sc1;
        sc1 = fminf(2.f, fmaxf(-2.f, sc1));
        float s1 = __expf(sc1);

        int p0 = atomicAdd(&g_cnt[e.x], 1);
        g_csr[(size_t)e.x * CAP + p0] = make_int2(e.y, __float_as_int(s0));
        int p1 = atomicAdd(&g_cnt[e.z], 1);
        g_csr[(size_t)e.z * CAP + p1] = make_int2(e.w, __float_as_int(s1));
    }
}

// ---------------------------------------------------------------------------
// One warp per dst node: gather fp16 h[src] via per-lane uint2, packed
// f32x2 FFMA accumulation, int4 metadata loads (2 edges/load), normalize.
// ---------------------------------------------------------------------------
__global__ __launch_bounds__(256) void agg_kernel(float* __restrict__ out) {
    int w    = (blockIdx.x * blockDim.x + threadIdx.x) >> 5;
    int lane = threadIdx.x & 31;
    if (w >= N_NODES) return;

    int cnt = g_cnt[w];
    const int2* row = g_csr + (size_t)w * CAP;
    const uint2* hh = reinterpret_cast<const uint2*>(g_hh);

    unsigned long long accA = 0ull, accB = 0ull;   // packed (c0,c1), (c2,c3)
    float ssum = 0.f;

    #define ACCUM(V, WT) { \
        float2 f0 = __half22float2(*reinterpret_cast<__half2*>(&(V).x)); \
        float2 f1 = __half22float2(*reinterpret_cast<__half2*>(&(V).y)); \
        unsigned long long ww = pack_f2(make_float2((WT), (WT))); \
        FMA_F32X2(accA, ww, pack_f2(f0), accA); \
        FMA_F32X2(accB, ww, pack_f2(f1), accB); }

    int e = 0;
    for (; e + 4 <= cnt; e += 4) {
        int4 m01 = *reinterpret_cast<const int4*>(row + e);
        int4 m23 = *reinterpret_cast<const int4*>(row + e + 2);
        float w0 = __int_as_float(m01.y), w1 = __int_as_float(m01.w);
        float w2 = __int_as_float(m23.y), w3 = __int_as_float(m23.w);
        uint2 v0 = hh[(size_t)m01.x * 32 + lane];
        uint2 v1 = hh[(size_t)m01.z * 32 + lane];
        uint2 v2 = hh[(size_t)m23.x * 32 + lane];
        uint2 v3 = hh[(size_t)m23.z * 32 + lane];
        ACCUM(v0, w0) ACCUM(v1, w1) ACCUM(v2, w2) ACCUM(v3, w3)
        ssum += (w0 + w1) + (w2 + w3);
    }
    for (; e < cnt; e++) {
        int2 ee = row[e];
        float w0 = __int_as_float(ee.y);
        uint2 v0 = hh[(size_t)ee.x * 32 + lane];
        ACCUM(v0, w0)
        ssum += w0;
    }
    #undef ACCUM

    float2 rA = *reinterpret_cast<float2*>(&accA);
    float2 rB = *reinterpret_cast<float2*>(&accB);
    float inv = (ssum > 0.f) ? (1.f / ssum) : 0.f;
    reinterpret_cast<float4*>(out)[(size_t)w * 32 + lane] =
        make_float4(rA.x * inv, rA.y * inv, rB.x * inv, rB.y * inv);
}

// ---------------------------------------------------------------------------
extern "C" void kernel_launch(void* const* d_in, const int* in_sizes, int n_in,
                              void* d_out, int out_size)
{
    const float* X    = (const float*)d_in[0];   // node_states (50000,128)
    const int4*  E4   = (const int4*) d_in[1];   // edges as 2-edge packs
    const float* W    = (const float*)d_in[2];   // kernel (128,128)
    const float* attn = (const float*)d_in[3];   // kernel_attention (256,1)
    float* out = (float*)d_out;

    setup_kernel<<<PACK_BLOCKS + WDWS_BLOCKS, 256>>>(W, attn);
    score_kernel<<<(N_NODES * 32 + 255) / 256, 256>>>(X);
    fused_kernel<<<GEMM_BLOCKS + SCAT_BLOCKS, 256>>>(X, E4);
    agg_kernel<<<(N_NODES * 32 + 255) / 256, 256>>>(out);
}